// round 14
// baseline (speedup 1.0000x reference)
#include <cuda_runtime.h>
#include <math.h>
#include <stdint.h>

#define Bsz 256
#define Tsz 512
#define Dsz 256
#define Ksz 256

__device__ float g_xU[Bsz * Tsz * Ksz];   // 128 MB scratch for xU = x@U + b

// ===========================================================================
// Helpers
// ===========================================================================
__device__ __forceinline__ unsigned long long pack2(float lo, float hi) {
    unsigned long long r;
    asm("mov.b64 %0, {%1, %2};" : "=l"(r) : "f"(lo), "f"(hi));
    return r;
}
__device__ __forceinline__ void unpack2(unsigned long long v, float& lo, float& hi) {
    asm("mov.b64 {%0, %1}, %2;" : "=f"(lo), "=f"(hi) : "l"(v));
}
__device__ __forceinline__ void fma2(unsigned long long& acc, unsigned long long h, unsigned long long w) {
    asm("fma.rn.f32x2 %0, %1, %2, %0;" : "+l"(acc) : "l"(h), "l"(w));
}
__device__ __forceinline__ unsigned long long add2v(unsigned long long a, unsigned long long b) {
    unsigned long long r;
    asm("add.rn.f32x2 %0, %1, %2;" : "=l"(r) : "l"(a), "l"(b));
    return r;
}
__device__ __forceinline__ uint32_t f2tf32(float f) {
    uint32_t r;
    asm("cvt.rna.tf32.f32 %0, %1;" : "=r"(r) : "f"(f));
    return r;
}
__device__ __forceinline__ void mma_tf32(float* c, const uint32_t* a, const uint32_t* b) {
    asm("mma.sync.aligned.m16n8k8.row.col.f32.tf32.tf32.f32 "
        "{%0,%1,%2,%3}, {%4,%5,%6,%7}, {%8,%9}, {%0,%1,%2,%3};"
        : "+f"(c[0]), "+f"(c[1]), "+f"(c[2]), "+f"(c[3])
        : "r"(a[0]), "r"(a[1]), "r"(a[2]), "r"(a[3]), "r"(b[0]), "r"(b[1]));
}
__device__ __forceinline__ uint32_t smem_u32(const void* p) {
    uint32_t a;
    asm("{ .reg .u64 t; cvta.to.shared.u64 t, %1; cvt.u32.u64 %0, t; }" : "=r"(a) : "l"(p));
    return a;
}

// ===========================================================================
// Kernel A: xU = X @ U + b   — tf32 tensor cores (unchanged)
// ===========================================================================
__global__ void __launch_bounds__(256) gemm_xu_tc(
    const float* __restrict__ X,
    const float* __restrict__ U,
    const float* __restrict__ bias,
    float* __restrict__ out)
{
    __shared__ float As[128][36];
    __shared__ float Bs[32][132];

    const int tid  = threadIdx.x;
    const int wid  = tid >> 5;
    const int lane = tid & 31;
    const int wm   = (wid & 3) * 32;
    const int wn   = (wid >> 2) * 64;
    const int row0 = blockIdx.y * 128;
    const int col0 = blockIdx.x * 128;

    float acc[2][8][4];
    #pragma unroll
    for (int mt = 0; mt < 2; mt++)
        #pragma unroll
        for (int nt = 0; nt < 8; nt++)
            #pragma unroll
            for (int i = 0; i < 4; i++) acc[mt][nt][i] = 0.0f;

    const int ar = lane >> 2;
    const int ac = lane & 3;
    const int bk = lane & 3;
    const int bn = lane >> 2;

    for (int kb = 0; kb < Dsz; kb += 32) {
        #pragma unroll
        for (int i = 0; i < 4; i++) {
            int lin = tid + i * 256;
            int m = lin >> 3, k = (lin & 7) << 2;
            float4 v = *(const float4*)&X[(size_t)(row0 + m) * Dsz + kb + k];
            v.x = __uint_as_float(f2tf32(v.x));
            v.y = __uint_as_float(f2tf32(v.y));
            v.z = __uint_as_float(f2tf32(v.z));
            v.w = __uint_as_float(f2tf32(v.w));
            *(float4*)&As[m][k] = v;

            int k2 = lin >> 5, n = (lin & 31) << 2;
            float4 u = *(const float4*)&U[(size_t)(kb + k2) * Ksz + col0 + n];
            u.x = __uint_as_float(f2tf32(u.x));
            u.y = __uint_as_float(f2tf32(u.y));
            u.z = __uint_as_float(f2tf32(u.z));
            u.w = __uint_as_float(f2tf32(u.w));
            *(float4*)&Bs[k2][n] = u;
        }
        __syncthreads();

        #pragma unroll
        for (int kc = 0; kc < 4; kc++) {
            const int k0 = kc * 8;
            uint32_t af[2][4];
            #pragma unroll
            for (int mt = 0; mt < 2; mt++) {
                const int mb = wm + mt * 16;
                af[mt][0] = __float_as_uint(As[mb + ar    ][k0 + ac    ]);
                af[mt][1] = __float_as_uint(As[mb + ar + 8][k0 + ac    ]);
                af[mt][2] = __float_as_uint(As[mb + ar    ][k0 + ac + 4]);
                af[mt][3] = __float_as_uint(As[mb + ar + 8][k0 + ac + 4]);
            }
            #pragma unroll
            for (int nt = 0; nt < 8; nt++) {
                uint32_t bf[2];
                const int nb = wn + nt * 8 + bn;
                bf[0] = __float_as_uint(Bs[k0 + bk    ][nb]);
                bf[1] = __float_as_uint(Bs[k0 + bk + 4][nb]);
                mma_tf32(acc[0][nt], af[0], bf);
                mma_tf32(acc[1][nt], af[1], bf);
            }
        }
        __syncthreads();
    }

    #pragma unroll
    for (int nt = 0; nt < 8; nt++) {
        const int cb = col0 + wn + nt * 8 + 2 * (lane & 3);
        float2 bb = *(const float2*)&bias[cb];
        #pragma unroll
        for (int mt = 0; mt < 2; mt++) {
            const int r = row0 + wm + mt * 16 + (lane >> 2);
            float2 o0 = { acc[mt][nt][0] + bb.x, acc[mt][nt][1] + bb.y };
            float2 o1 = { acc[mt][nt][2] + bb.x, acc[mt][nt][3] + bb.y };
            *(float2*)&out[(size_t)r       * Ksz + cb] = o0;
            *(float2*)&out[(size_t)(r + 8) * Ksz + cb] = o1;
        }
    }
}

// ===========================================================================
// Kernel B (R14): recurrence. 64 clusters x 2 CTAs x 512 threads; 4 rows.
// NC=8: warp wid owns 8 cols [rank*128 + wid*8, +8); lane owns d-slice
// {lane, 32+lane, ..., 224+lane} (8 d), all 4 rows -> 8 LDS.128/thread/step
// (half of R13's crossbar bytes). 128 FMA2/thread (the pipe floor).
// Butterfly: 5 shfl rounds over the full warp; lane L ends owning output
// (row = L>>3, col = c0 + (L&7)). tanh/xu/stores fully distributed.
// Sync: __syncthreads + single tid0 remote mbarrier arrive (count=1) +
// all-thread acquire try_wait. No cluster barrier in the loop.
// ===========================================================================
__global__ void __launch_bounds__(512, 1) __cluster_dims__(2, 1, 1)
rnn_rec14_kernel(const float* __restrict__ xU,
                 const float* __restrict__ W,
                 float* __restrict__ out)
{
    __shared__ alignas(16) float hb[2][Ksz][4];   // [buf][d][row] = 8 KB
    __shared__ unsigned long long mbar[2];

    const int tid  = threadIdx.x;
    const int wid  = tid >> 5;                  // colgroup 0..15
    const int lane = tid & 31;

    uint32_t rank;
    asm("mov.u32 %0, %%cluster_ctarank;" : "=r"(rank));
    const uint32_t peer = rank ^ 1u;
    const int c0  = ((int)rank << 7) + wid * 8;      // warp's first col
    const int b0  = (blockIdx.x >> 1) * 4;

    // this lane's final output identity
    const int row = lane >> 3;                  // 0..3
    const int cg  = c0 + (lane & 7);            // global column

    // W pack: Wp[j][cp] = (W[32j+lane][c0+2cp], W[32j+lane][c0+2cp+1])
    unsigned long long Wp[8][4];
    #pragma unroll
    for (int j = 0; j < 8; j++) {
        const float* wr = &W[(size_t)(32 * j + lane) * Ksz + c0];
        Wp[j][0] = pack2(wr[0], wr[1]);
        Wp[j][1] = pack2(wr[2], wr[3]);
        Wp[j][2] = pack2(wr[4], wr[5]);
        Wp[j][3] = pack2(wr[6], wr[7]);
    }

    // zero h buffers; init mbarriers (count = 1: single remote arriver)
    for (int i = tid; i < 2 * Ksz * 4; i += 512) ((float*)hb)[i] = 0.0f;
    if (tid == 0) {
        asm volatile("mbarrier.init.shared.b64 [%0], 1;" :: "r"(smem_u32(&mbar[0])) : "memory");
        asm volatile("mbarrier.init.shared.b64 [%0], 1;" :: "r"(smem_u32(&mbar[1])) : "memory");
    }
    __syncthreads();
    asm volatile("barrier.cluster.arrive.aligned;" ::: "memory");
    asm volatile("barrier.cluster.wait.aligned;"   ::: "memory");

    uint32_t mbL[2], mbP[2];
    #pragma unroll
    for (int p = 0; p < 2; p++) {
        mbL[p] = smem_u32(&mbar[p]);
        asm("mapa.shared::cluster.u32 %0, %1, %2;" : "=r"(mbP[p]) : "r"(mbL[p]), "r"(peer));
    }
    // read base: &hb[buf][lane][0], j advances 32 d = 512 bytes
    uint32_t rdL[2] = { smem_u32(&hb[0][lane][0]), smem_u32(&hb[1][lane][0]) };
    // write slot: &hb[p][cg][row], local + peer
    uint32_t wrL[2], wrP[2];
    #pragma unroll
    for (int p = 0; p < 2; p++) {
        uint32_t a = smem_u32(&hb[p][cg][row]);
        wrL[p] = a;
        asm("mapa.shared::cluster.u32 %0, %1, %2;" : "=r"(wrP[p]) : "r"(a), "r"(peer));
    }

    const float* xp = xU + (size_t)(b0 + row) * Tsz * Ksz + cg;
    float xu = xp[0];
    float hv = 0.0f;
    int ph[2] = {0, 0};

    const unsigned rb0 = (lane >> 3) & 1;   // row bit0
    const unsigned rb1 = (lane >> 4) & 1;   // row bit1
    const unsigned cb1 = (lane >> 2) & 1;   // col-pair bit1
    const unsigned cb0 = (lane >> 1) & 1;   // col-pair bit0
    const unsigned pb  = lane & 1;          // f32x2 parity

    for (int t = 0; t < Tsz; t++) {
        const int buf = t & 1;
        if (t) {
            uint32_t mb = mbL[buf];
            int phase = ph[buf];
            ph[buf] ^= 1;
            asm volatile(
                "{\n\t"
                ".reg .pred P;\n\t"
                "WL_%=:\n\t"
                "mbarrier.try_wait.parity.acquire.cluster.shared::cta.b64 P, [%0], %1, 0x989680;\n\t"
                "@P bra.uni WD_%=;\n\t"
                "bra.uni WL_%=;\n\t"
                "WD_%=:\n\t"
                "}"
                :: "r"(mb), "r"(phase) : "memory");
        }

        const uint32_t rb = rdL[buf];
        // accs a[cp][r]; 8 j-iters x (1 LDS.128 + 4 pack + 16 FMA2)
        unsigned long long a[4][4];
        #pragma unroll
        for (int cp = 0; cp < 4; cp++)
            #pragma unroll
            for (int r = 0; r < 4; r++) a[cp][r] = 0ull;

        #pragma unroll
        for (int j = 0; j < 8; j++) {
            uint32_t h0, h1, h2, h3;
            asm("ld.shared.v4.b32 {%0,%1,%2,%3}, [%4];"
                : "=r"(h0), "=r"(h1), "=r"(h2), "=r"(h3) : "r"(rb + j * 512));
            unsigned long long hd0 = ((unsigned long long)h0 << 32) | h0;
            unsigned long long hd1 = ((unsigned long long)h1 << 32) | h1;
            unsigned long long hd2 = ((unsigned long long)h2 << 32) | h2;
            unsigned long long hd3 = ((unsigned long long)h3 << 32) | h3;
            #pragma unroll
            for (int cp = 0; cp < 4; cp++) {
                fma2(a[cp][0], hd0, Wp[j][cp]);
                fma2(a[cp][1], hd1, Wp[j][cp]);
                fma2(a[cp][2], hd2, Wp[j][cp]);
                fma2(a[cp][3], hd3, Wp[j][cp]);
            }
        }

        // ---- 5-round recursive-halving butterfly over the warp ----
        // mask 8 (row bit0): keep rows {rb0, rb0+2}
        unsigned long long t8[4][2];
        #pragma unroll
        for (int cp = 0; cp < 4; cp++)
            #pragma unroll
            for (int k = 0; k < 2; k++) {
                unsigned long long keep = rb0 ? a[cp][1 + 2 * k] : a[cp][0 + 2 * k];
                unsigned long long send = rb0 ? a[cp][0 + 2 * k] : a[cp][1 + 2 * k];
                unsigned long long got  = __shfl_xor_sync(0xffffffffu, send, 8);
                t8[cp][k] = add2v(keep, got);
            }
        // mask 16 (row bit1): keep k = rb1
        unsigned long long t16[4];
        #pragma unroll
        for (int cp = 0; cp < 4; cp++) {
            unsigned long long keep = rb1 ? t8[cp][1] : t8[cp][0];
            unsigned long long send = rb1 ? t8[cp][0] : t8[cp][1];
            unsigned long long got  = __shfl_xor_sync(0xffffffffu, send, 16);
            t16[cp] = add2v(keep, got);
        }
        // mask 4 (cp bit1): keep cp in {2*cb1, 2*cb1+1}
        unsigned long long t4[2];
        #pragma unroll
        for (int k = 0; k < 2; k++) {
            unsigned long long keep = cb1 ? t16[2 + k] : t16[k];
            unsigned long long send = cb1 ? t16[k]     : t16[2 + k];
            unsigned long long got  = __shfl_xor_sync(0xffffffffu, send, 4);
            t4[k] = add2v(keep, got);
        }
        // mask 2 (cp bit0): keep k = cb0
        unsigned long long t2;
        {
            unsigned long long keep = cb0 ? t4[1] : t4[0];
            unsigned long long send = cb0 ? t4[0] : t4[1];
            unsigned long long got  = __shfl_xor_sync(0xffffffffu, send, 2);
            t2 = add2v(keep, got);
        }
        // mask 1 (parity): exchange full pair, add, select half
        {
            unsigned long long got = __shfl_xor_sync(0xffffffffu, t2, 1);
            t2 = add2v(t2, got);
        }
        float lo, hi;
        unpack2(t2, lo, hi);
        float s = pb ? hi : lo;

        s += xu;
        const int wr = (t + 1 < Tsz);
        xu = xp[(size_t)(wr ? t + 1 : t) * Ksz];   // prefetch
        hv = tanhf(s);

        const int pn = (t + 1) & 1;
        if (wr) {
            asm volatile("st.shared.f32 [%0], %1;" :: "r"(wrL[pn]), "f"(hv) : "memory");
            asm volatile("st.shared::cluster.f32 [%0], %1;" :: "r"(wrP[pn]), "f"(hv) : "memory");
        }
        __syncthreads();   // all local+remote stores of step t ordered before arrive
        if (wr && tid == 0) {
            asm volatile("mbarrier.arrive.release.cluster.shared::cluster.b64 _, [%0];"
                         :: "r"(mbP[pn]) : "memory");
        }
    }

    out[(size_t)(b0 + row) * Ksz + cg] = hv;
}

// ===========================================================================
// Launch
// ===========================================================================
extern "C" void kernel_launch(void* const* d_in, const int* in_sizes, int n_in,
                              void* d_out, int out_size)
{
    const float* x    = (const float*)d_in[0];   // [256, 512, 256]
    const float* U    = (const float*)d_in[1];   // [256, 256]
    const float* W    = (const float*)d_in[2];   // [256, 256]
    const float* bias = (const float*)d_in[3];   // [256]
    float* out        = (float*)d_out;           // [256, 1, 256]

    float* xU;
    cudaGetSymbolAddress((void**)&xU, g_xU);

    dim3 gridA(Ksz / 128, (Bsz * Tsz) / 128);    // (2, 1024)
    gemm_xu_tc<<<gridA, 256>>>(x, U, bias, xU);

    rnn_rec14_kernel<<<(Bsz / 4) * 2, 512>>>(xU, W, out);
}

// round 15
// speedup vs baseline: 1.3076x; 1.3076x over previous
#include <cuda_runtime.h>
#include <math.h>
#include <stdint.h>

#define Bsz 256
#define Tsz 512
#define Dsz 256
#define Ksz 256

__device__ float g_xU[Bsz * Tsz * Ksz];   // 128 MB scratch for xU = x@U + b

// ===========================================================================
// Helpers
// ===========================================================================
__device__ __forceinline__ unsigned long long pack2(float lo, float hi) {
    unsigned long long r;
    asm("mov.b64 %0, {%1, %2};" : "=l"(r) : "f"(lo), "f"(hi));
    return r;
}
__device__ __forceinline__ void unpack2(unsigned long long v, float& lo, float& hi) {
    asm("mov.b64 {%0, %1}, %2;" : "=f"(lo), "=f"(hi) : "l"(v));
}
__device__ __forceinline__ void fma2(unsigned long long& acc, unsigned long long h, unsigned long long w) {
    asm("fma.rn.f32x2 %0, %1, %2, %0;" : "+l"(acc) : "l"(h), "l"(w));
}
__device__ __forceinline__ unsigned long long add2v(unsigned long long a, unsigned long long b) {
    unsigned long long r;
    asm("add.rn.f32x2 %0, %1, %2;" : "=l"(r) : "l"(a), "l"(b));
    return r;
}
__device__ __forceinline__ uint32_t f2tf32(float f) {
    uint32_t r;
    asm("cvt.rna.tf32.f32 %0, %1;" : "=r"(r) : "f"(f));
    return r;
}
__device__ __forceinline__ void mma_tf32(float* c, const uint32_t* a, const uint32_t* b) {
    asm("mma.sync.aligned.m16n8k8.row.col.f32.tf32.tf32.f32 "
        "{%0,%1,%2,%3}, {%4,%5,%6,%7}, {%8,%9}, {%0,%1,%2,%3};"
        : "+f"(c[0]), "+f"(c[1]), "+f"(c[2]), "+f"(c[3])
        : "r"(a[0]), "r"(a[1]), "r"(a[2]), "r"(a[3]), "r"(b[0]), "r"(b[1]));
}
__device__ __forceinline__ uint32_t smem_u32(const void* p) {
    uint32_t a;
    asm("{ .reg .u64 t; cvta.to.shared.u64 t, %1; cvt.u32.u64 %0, t; }" : "=r"(a) : "l"(p));
    return a;
}

// ===========================================================================
// Kernel A (R15): xU = X @ U + b — tf32 mma, BK=32, double-buffered smem.
// LDGs for tile k+1 are issued before computing tile k (latency hidden);
// one __syncthreads per 32-K chunk. Dynamic smem (70.6 KB).
// ===========================================================================
#define GA_PITCH 36     // As row pitch (floats)
#define GB_PITCH 132    // Bs row pitch (floats)
#define GA_BUF (128 * GA_PITCH)
#define GB_BUF (32 * GB_PITCH)
#define GEMM_SMEM_BYTES ((2 * GA_BUF + 2 * GB_BUF) * 4)

extern __shared__ float g_smem[];

__global__ void __launch_bounds__(256) gemm_xu_tc(
    const float* __restrict__ X,
    const float* __restrict__ U,
    const float* __restrict__ bias,
    float* __restrict__ out)
{
    float* As = g_smem;                    // [2][128][36]
    float* Bs = g_smem + 2 * GA_BUF;       // [2][32][132]

    const int tid  = threadIdx.x;
    const int wid  = tid >> 5;
    const int lane = tid & 31;
    const int wm   = (wid & 3) * 32;
    const int wn   = (wid >> 2) * 64;
    const int row0 = blockIdx.y * 128;
    const int col0 = blockIdx.x * 128;

    float acc[2][8][4];
    #pragma unroll
    for (int mt = 0; mt < 2; mt++)
        #pragma unroll
        for (int nt = 0; nt < 8; nt++)
            #pragma unroll
            for (int i = 0; i < 4; i++) acc[mt][nt][i] = 0.0f;

    const int ar = lane >> 2;
    const int ac = lane & 3;
    const int bk = lane & 3;
    const int bn = lane >> 2;

    // load mappings: 4 float4 per thread for each of A and B
    int amr[4], akc[4], bkr[4], bnc[4];
    #pragma unroll
    for (int i = 0; i < 4; i++) {
        int lin = tid + i * 256;
        amr[i] = lin >> 3;            // A row 0..127
        akc[i] = (lin & 7) << 2;      // A k 0..28
        bkr[i] = lin >> 5;            // B k 0..31
        bnc[i] = (lin & 31) << 2;     // B n 0..124
    }

    float4 pa[4], pb[4];
    // prefetch tile 0
    #pragma unroll
    for (int i = 0; i < 4; i++) {
        pa[i] = *(const float4*)&X[(size_t)(row0 + amr[i]) * Dsz + akc[i]];
        pb[i] = *(const float4*)&U[(size_t)bkr[i] * Ksz + col0 + bnc[i]];
    }

    #pragma unroll 1
    for (int kb = 0; kb < 8; kb++) {
        const int cur = kb & 1;
        float* Ac = As + cur * GA_BUF;
        float* Bc = Bs + cur * GB_BUF;

        // store prefetched tile kb (convert to tf32)
        #pragma unroll
        for (int i = 0; i < 4; i++) {
            float4 v = pa[i];
            v.x = __uint_as_float(f2tf32(v.x));
            v.y = __uint_as_float(f2tf32(v.y));
            v.z = __uint_as_float(f2tf32(v.z));
            v.w = __uint_as_float(f2tf32(v.w));
            *(float4*)&Ac[amr[i] * GA_PITCH + akc[i]] = v;
            float4 u = pb[i];
            u.x = __uint_as_float(f2tf32(u.x));
            u.y = __uint_as_float(f2tf32(u.y));
            u.z = __uint_as_float(f2tf32(u.z));
            u.w = __uint_as_float(f2tf32(u.w));
            *(float4*)&Bc[bkr[i] * GB_PITCH + bnc[i]] = u;
        }
        __syncthreads();

        // issue LDGs for tile kb+1 (latency overlaps compute below)
        if (kb < 7) {
            const int k0g = (kb + 1) * 32;
            #pragma unroll
            for (int i = 0; i < 4; i++) {
                pa[i] = *(const float4*)&X[(size_t)(row0 + amr[i]) * Dsz + k0g + akc[i]];
                pb[i] = *(const float4*)&U[(size_t)(k0g + bkr[i]) * Ksz + col0 + bnc[i]];
            }
        }

        // compute tile kb: 4 kc chunks of 8 k
        #pragma unroll
        for (int kc = 0; kc < 4; kc++) {
            const int k0 = kc * 8;
            uint32_t af[2][4];
            #pragma unroll
            for (int mt = 0; mt < 2; mt++) {
                const int mb = wm + mt * 16;
                af[mt][0] = __float_as_uint(Ac[(mb + ar    ) * GA_PITCH + k0 + ac    ]);
                af[mt][1] = __float_as_uint(Ac[(mb + ar + 8) * GA_PITCH + k0 + ac    ]);
                af[mt][2] = __float_as_uint(Ac[(mb + ar    ) * GA_PITCH + k0 + ac + 4]);
                af[mt][3] = __float_as_uint(Ac[(mb + ar + 8) * GA_PITCH + k0 + ac + 4]);
            }
            #pragma unroll
            for (int nt = 0; nt < 8; nt++) {
                uint32_t bf[2];
                const int nb = wn + nt * 8 + bn;
                bf[0] = __float_as_uint(Bc[(k0 + bk    ) * GB_PITCH + nb]);
                bf[1] = __float_as_uint(Bc[(k0 + bk + 4) * GB_PITCH + nb]);
                mma_tf32(acc[0][nt], af[0], bf);
                mma_tf32(acc[1][nt], af[1], bf);
            }
        }
        __syncthreads();
    }

    #pragma unroll
    for (int nt = 0; nt < 8; nt++) {
        const int cb = col0 + wn + nt * 8 + 2 * (lane & 3);
        float2 bb = *(const float2*)&bias[cb];
        #pragma unroll
        for (int mt = 0; mt < 2; mt++) {
            const int r = row0 + wm + mt * 16 + (lane >> 2);
            float2 o0 = { acc[mt][nt][0] + bb.x, acc[mt][nt][1] + bb.y };
            float2 o1 = { acc[mt][nt][2] + bb.x, acc[mt][nt][3] + bb.y };
            *(float2*)&out[(size_t)r       * Ksz + cb] = o0;
            *(float2*)&out[(size_t)(r + 8) * Ksz + cb] = o1;
        }
    }
}

// ===========================================================================
// Kernel B: recurrence — EXACT R13 (measured 862 us). 64 clusters x 2 CTAs
// x 512 threads; NC=4 col-reuse, 16-lane butterfly, full cluster barrier.
// ===========================================================================
__global__ void __launch_bounds__(512, 1) __cluster_dims__(2, 1, 1)
rnn_rec13_kernel(const float* __restrict__ xU,
                 const float* __restrict__ W,
                 float* __restrict__ out)
{
    __shared__ alignas(16) float hb[2][Ksz][4];   // [buf][d][row] = 8 KB

    const int tid  = threadIdx.x;
    const int w    = tid >> 5;                  // 0..15
    const int lane = tid & 31;
    const int q    = lane & 15;                 // d-slice id
    const int c2   = lane >> 4;                 // 0..1
    const int cq   = w * 2 + c2;                // colgroup 0..31 (4 cols each)

    uint32_t rank;
    asm("mov.u32 %0, %%cluster_ctarank;" : "=r"(rank));
    const uint32_t peer = rank ^ 1u;
    const int cbase = ((int)rank << 7) + cq * 4;     // first of 4 owned cols
    const int b0 = (blockIdx.x >> 1) * 4;            // 4 batch rows per cluster

    // Output identity after reduction: this lane owns (row, col):
    const int row    = 2 * (q & 1) + ((q >> 1) & 1);
    const int colofs = 2 * ((q >> 2) & 1) + ((q >> 3) & 1);
    const int cg     = cbase + colofs;

    // W pack: Wp[j][cp] = (W[16j+q][cbase+2cp], W[16j+q][cbase+2cp+1])
    unsigned long long Wp[16][2];
    #pragma unroll
    for (int j = 0; j < 16; j++) {
        const float* wr = &W[(size_t)(16 * j + q) * Ksz + cbase];
        Wp[j][0] = pack2(wr[0], wr[1]);
        Wp[j][1] = pack2(wr[2], wr[3]);
    }

    // zero h buffers
    for (int i = tid; i < 2 * Ksz * 4; i += 512) ((float*)hb)[i] = 0.0f;
    __syncthreads();
    asm volatile("barrier.cluster.arrive.aligned;" ::: "memory");
    asm volatile("barrier.cluster.wait.aligned;"   ::: "memory");

    // read base: &hb[buf][q][0]; j advances by 16 d = 256 bytes
    uint32_t rdL[2] = { smem_u32(&hb[0][q][0]), smem_u32(&hb[1][q][0]) };
    // write slot: &hb[p][cg][row] local + peer
    uint32_t wrL[2], wrP[2];
    #pragma unroll
    for (int p = 0; p < 2; p++) {
        uint32_t a = smem_u32(&hb[p][cg][row]);
        wrL[p] = a;
        asm("mapa.shared::cluster.u32 %0, %1, %2;" : "=r"(wrP[p]) : "r"(a), "r"(peer));
    }

    // xu pointer for this lane's (row, col)
    const float* xp = xU + (size_t)(b0 + row) * Tsz * Ksz + cg;
    float xu = xp[0];
    float hv = 0.0f;

    for (int t = 0; t < Tsz; t++) {
        const uint32_t rb = rdL[t & 1];

        // 16 j-iters: LDS.128 (h[d][r0..r3]) + 4 dup-packs + 8 FMA2
        unsigned long long a[2][4];
        #pragma unroll
        for (int cp = 0; cp < 2; cp++)
            #pragma unroll
            for (int r = 0; r < 4; r++) a[cp][r] = 0ull;

        #pragma unroll
        for (int j = 0; j < 16; j++) {
            uint32_t h0, h1, h2, h3;
            asm("ld.shared.v4.b32 {%0,%1,%2,%3}, [%4];"
                : "=r"(h0), "=r"(h1), "=r"(h2), "=r"(h3) : "r"(rb + j * 256));
            unsigned long long hd0 = ((unsigned long long)h0 << 32) | h0;
            unsigned long long hd1 = ((unsigned long long)h1 << 32) | h1;
            unsigned long long hd2 = ((unsigned long long)h2 << 32) | h2;
            unsigned long long hd3 = ((unsigned long long)h3 << 32) | h3;
            fma2(a[0][0], hd0, Wp[j][0]); fma2(a[1][0], hd0, Wp[j][1]);
            fma2(a[0][1], hd1, Wp[j][0]); fma2(a[1][1], hd1, Wp[j][1]);
            fma2(a[0][2], hd2, Wp[j][0]); fma2(a[1][2], hd2, Wp[j][1]);
            fma2(a[0][3], hd3, Wp[j][0]); fma2(a[1][3], hd3, Wp[j][1]);
        }

        // ---- recursive-halving butterfly over the 16 q-lanes ----
        const unsigned b0q = q & 1, b1q = q & 2, b2q = q & 4;
        // Round 1 (mask 1): keep rows {0,1} if bit0=0 else {2,3}
        unsigned long long r1[2][2];
        #pragma unroll
        for (int cp = 0; cp < 2; cp++)
            #pragma unroll
            for (int k = 0; k < 2; k++) {
                unsigned long long send = b0q ? a[cp][k] : a[cp][2 + k];
                unsigned long long keep = b0q ? a[cp][2 + k] : a[cp][k];
                unsigned long long got  = __shfl_xor_sync(0xffffffffu, send, 1);
                r1[cp][k] = add2v(keep, got);
            }
        // Round 2 (mask 2): keep k=0 if bit1=0 else k=1
        unsigned long long r2[2];
        #pragma unroll
        for (int cp = 0; cp < 2; cp++) {
            unsigned long long send = b1q ? r1[cp][0] : r1[cp][1];
            unsigned long long keep = b1q ? r1[cp][1] : r1[cp][0];
            unsigned long long got  = __shfl_xor_sync(0xffffffffu, send, 2);
            r2[cp] = add2v(keep, got);
        }
        // Round 3 (mask 4): keep cp=0 if bit2=0 else cp=1
        {
            unsigned long long send = b2q ? r2[0] : r2[1];
            unsigned long long keep = b2q ? r2[1] : r2[0];
            unsigned long long got  = __shfl_xor_sync(0xffffffffu, send, 4);
            r2[0] = add2v(keep, got);
        }
        // Round 4 (mask 8): complete 16-lane sum
        {
            unsigned long long got = __shfl_xor_sync(0xffffffffu, r2[0], 8);
            r2[0] = add2v(r2[0], got);
        }
        float lo, hi;
        unpack2(r2[0], lo, hi);
        float s = (q & 8) ? hi : lo;

        s += xu;
        const int wrS = (t + 1 < Tsz);
        xu = xp[(size_t)(wrS ? t + 1 : t) * Ksz];   // prefetch next step
        hv = tanhf(s);

        if (wrS) {
            const int pn = (t + 1) & 1;
            asm volatile("st.shared.f32 [%0], %1;" :: "r"(wrL[pn]), "f"(hv) : "memory");
            asm volatile("st.shared::cluster.f32 [%0], %1;" :: "r"(wrP[pn]), "f"(hv) : "memory");
        }
        asm volatile("barrier.cluster.arrive.aligned;" ::: "memory");
        asm volatile("barrier.cluster.wait.aligned;"   ::: "memory");
    }

    out[(size_t)(b0 + row) * Ksz + cg] = hv;
}

// ===========================================================================
// Launch
// ===========================================================================
extern "C" void kernel_launch(void* const* d_in, const int* in_sizes, int n_in,
                              void* d_out, int out_size)
{
    const float* x    = (const float*)d_in[0];   // [256, 512, 256]
    const float* U    = (const float*)d_in[1];   // [256, 256]
    const float* W    = (const float*)d_in[2];   // [256, 256]
    const float* bias = (const float*)d_in[3];   // [256]
    float* out        = (float*)d_out;           // [256, 1, 256]

    float* xU;
    cudaGetSymbolAddress((void**)&xU, g_xU);

    cudaFuncSetAttribute(gemm_xu_tc,
                         cudaFuncAttributeMaxDynamicSharedMemorySize,
                         GEMM_SMEM_BYTES);
    dim3 gridA(Ksz / 128, (Bsz * Tsz) / 128);    // (2, 1024)
    gemm_xu_tc<<<gridA, 256, GEMM_SMEM_BYTES>>>(x, U, bias, xU);

    rnn_rec13_kernel<<<(Bsz / 4) * 2, 512>>>(xU, W, out);
}